// round 12
// baseline (speedup 1.0000x reference)
#include <cuda_runtime.h>

#define NN 100000
#define MM 1000
#define KA 11     // A rank terms (k=0 of original folded into B slot 0)
#define KB 12     // B floats per m: [0]=c0*z0 (acc init), [1..11] pair with A[0..10]
#define TPB 256
#define VN 8      // n per thread (2x float4 store)
#define NP 4      // n-pairs per thread
#define MT 10     // m tiles
#define MC_MAX 100

typedef unsigned long long u64;

__device__ __forceinline__ u64 pack2(float lo, float hi) {
    u64 r; asm("mov.b64 %0, {%1,%2};" : "=l"(r) : "f"(lo), "f"(hi)); return r;
}
__device__ __forceinline__ u64 dup2(float v) {
    u64 r; asm("mov.b64 %0, {%1,%1};" : "=l"(r) : "f"(v)); return r;
}
__device__ __forceinline__ void unpack2(u64 v, float& lo, float& hi) {
    asm("mov.b64 {%0,%1}, %2;" : "=f"(lo), "=f"(hi) : "l"(v));
}
__device__ __forceinline__ u64 fma2(u64 a, u64 b, u64 c) {
    u64 d; asm("fma.rn.f32x2 %0, %1, %2, %3;" : "=l"(d) : "l"(a), "l"(b), "l"(c)); return d;
}
__device__ __forceinline__ float fast_sin(float x)  { float r; asm("sin.approx.f32 %0, %1;"  : "=f"(r) : "f"(x)); return r; }
__device__ __forceinline__ float fast_cos(float x)  { float r; asm("cos.approx.f32 %0, %1;"  : "=f"(r) : "f"(x)); return r; }
__device__ __forceinline__ float fast_tanh(float x) { float r; asm("tanh.approx.f32 %0, %1;" : "=f"(r) : "f"(x)); return r; }

// Fused rank-12 outer product, VN=8: halves per-byte LDS / dup-mov / store-issue
// overhead vs VN=4 at the cost of occupancy (128 regs, 2 blocks/SM).
//   out[m*NN + n] = c0*z0[m] + sum_{k=0..10} A[n,k] * B[m,k+1]
__global__ void __launch_bounds__(TPB, 2)
fused_kernel(const float* __restrict__ phi, const float* __restrict__ POD,
             const float* __restrict__ c, const float* __restrict__ omega,
             const float* __restrict__ z, const float* __restrict__ zsin,
             const float* __restrict__ zcos, const float* __restrict__ ztanh,
             const float* __restrict__ sc, const float* __restrict__ cc,
             const float* __restrict__ tc,
             float* __restrict__ out_final, float* __restrict__ out_latent,
             float* __restrict__ out_z) {
    __shared__ __align__(16) float Bs[MC_MAX * KB];  // plain floats, 48B per m

    const int tid = threadIdx.x;
    const int mBase = blockIdx.y * MC_MAX;            // y in [0,10); MC*MT == MM

    // ---- B tile: threads 0..MC_MAX-1 compute one m row each ----
    if (tid < MC_MAX) {
        int m = mBase + tid;
        float* b = Bs + tid * KB;
        b[0] = c[0] * z[m];
#pragma unroll
        for (int t = 1; t < 6; t++) b[t] = z[t * MM + m];
        b[6]  = sc[0] * zsin[m];
        b[7]  = sc[1] * zsin[MM + m];
        b[8]  = cc[0] * zcos[m];
        b[9]  = cc[1] * zcos[MM + m];
        b[10] = tc[0] * ztanh[m];
        b[11] = tc[1] * ztanh[MM + m];
    }

    // ---- z_values copy (once, by block (0,0)) ----
    if (blockIdx.x == 0 && blockIdx.y == 0) {
        for (int i = tid; i < 6 * MM; i += TPB) out_z[i] = z[i];
    }
    __syncthreads();

    const int n0 = (blockIdx.x * TPB + tid) * VN;
    if (n0 >= NN) return;  // NN % 8 == 0; in-range threads write 2 full float4

    // ---- A features inline for this thread's 8 n's ----
    float y0[VN], y1[VN];
#pragma unroll
    for (int h = 0; h < 2; h++) {           // two groups of 4 n
        float4 p0 = *(const float4*)(phi + n0 + 4 * h);
        float4 p1 = *(const float4*)(phi + NN + n0 + 4 * h);
        float4 qa = *(const float4*)(POD + 2 * (n0 + 4 * h));
        float4 qb = *(const float4*)(POD + 2 * (n0 + 4 * h) + 4);
        y0[4*h+0] = p0.x * qa.x;  y1[4*h+0] = p1.x * qa.y;
        y0[4*h+1] = p0.y * qa.z;  y1[4*h+1] = p1.y * qa.w;
        y0[4*h+2] = p0.z * qb.x;  y1[4*h+2] = p1.z * qb.y;
        y0[4*h+3] = p0.w * qb.z;  y1[4*h+3] = p1.w * qb.w;
    }

    if (blockIdx.y == 0) {  // latent_spatial (N,2): [y0, y1] interleaved
#pragma unroll
        for (int h = 0; h < 4; h++) {
            *(float4*)(out_latent + 2 * n0 + 4 * h) =
                make_float4(y0[2*h], y1[2*h], y0[2*h+1], y1[2*h+1]);
        }
    }

    float c1 = c[1], c2 = c[2], c3 = c[3], c4 = c[4], c5 = c[5];
    float w0 = omega[0], w1 = omega[1], w2 = omega[2];
    float w3 = omega[3], w4 = omega[4], w5 = omega[5];

    // Pack A features as f32x2 pairs: pa[p][k] covers n (2p, 2p+1).
    u64 pa[NP][KA];
#pragma unroll
    for (int p = 0; p < NP; p++) {
        int j0 = 2 * p, j1 = 2 * p + 1;
        pa[p][0]  = pack2(c1 * y0[j0],           c1 * y0[j1]);
        pa[p][1]  = pack2(c2 * y1[j0],           c2 * y1[j1]);
        pa[p][2]  = pack2(c3 * y0[j0] * y0[j0],  c3 * y0[j1] * y0[j1]);
        pa[p][3]  = pack2(c4 * y0[j0] * y1[j0],  c4 * y0[j1] * y1[j1]);
        pa[p][4]  = pack2(c5 * y1[j0] * y1[j0],  c5 * y1[j1] * y1[j1]);
        pa[p][5]  = pack2(fast_sin(w0 * y0[j0]), fast_sin(w0 * y0[j1]));
        pa[p][6]  = pack2(fast_sin(w3 * y1[j0]), fast_sin(w3 * y1[j1]));
        pa[p][7]  = pack2(fast_cos(w1 * y0[j0]), fast_cos(w1 * y0[j1]));
        pa[p][8]  = pack2(fast_cos(w4 * y1[j0]), fast_cos(w4 * y1[j1]));
        pa[p][9]  = pack2(fast_tanh(w2 * y0[j0]), fast_tanh(w2 * y0[j1]));
        pa[p][10] = pack2(fast_tanh(w5 * y1[j0]), fast_tanh(w5 * y1[j1]));
    }

    // ---- main store stream ----
    float* outBase = out_final + (size_t)mBase * NN + n0;
#pragma unroll 2
    for (int mi = 0; mi < MC_MAX; ++mi) {
        const float4* bb = (const float4*)(Bs + mi * KB);  // 3x LDS.128 (broadcast)
        float4 q0 = bb[0];   // b0..b3
        float4 q1 = bb[1];   // b4..b7
        float4 q2 = bb[2];   // b8..b11

        u64 acc[NP];
        u64 d0 = dup2(q0.x);                 // init = c0*z0[m]
        u64 d1 = dup2(q0.y);
#pragma unroll
        for (int p = 0; p < NP; p++) acc[p] = fma2(pa[p][0], d1, d0);

#define STEP(kk, BV)                                                          \
        {                                                                     \
            u64 dd = dup2(BV);                                                \
            _Pragma("unroll")                                                 \
            for (int p = 0; p < NP; p++) acc[p] = fma2(pa[p][kk], dd, acc[p]);\
        }
        STEP(1, q0.z)  STEP(2, q0.w)
        STEP(3, q1.x)  STEP(4, q1.y)  STEP(5, q1.z)  STEP(6, q1.w)
        STEP(7, q2.x)  STEP(8, q2.y)  STEP(9, q2.z)  STEP(10, q2.w)
#undef STEP

        float4 o1, o2;
        unpack2(acc[0], o1.x, o1.y);
        unpack2(acc[1], o1.z, o1.w);
        unpack2(acc[2], o2.x, o2.y);
        unpack2(acc[3], o2.z, o2.w);
        float* op = outBase + (size_t)mi * NN;
        __stcs((float4*)op, o1);
        __stcs((float4*)(op + 4), o2);
    }
}

extern "C" void kernel_launch(void* const* d_in, const int* in_sizes, int n_in,
                              void* d_out, int out_size) {
    // Input order: X, phi, POD_modes, c_coef, z_values, zsin, zcos,
    //              ztanh, sin_coef, cos_coef, tanh_coef, omega
    const float* phi   = (const float*)d_in[1];
    const float* POD   = (const float*)d_in[2];
    const float* c     = (const float*)d_in[3];
    const float* z     = (const float*)d_in[4];
    const float* zsin  = (const float*)d_in[5];
    const float* zcos  = (const float*)d_in[6];
    const float* ztanh = (const float*)d_in[7];
    const float* sc    = (const float*)d_in[8];
    const float* cc    = (const float*)d_in[9];
    const float* tc    = (const float*)d_in[10];
    const float* omega = (const float*)d_in[11];

    float* out        = (float*)d_out;
    float* out_final  = out;                              // (M, N)
    float* out_latent = out + (size_t)MM * NN;            // (N, 2)
    float* out_z      = out_latent + (size_t)NN * 2;      // (6, M)

    dim3 grid((NN + TPB * VN - 1) / (TPB * VN), MT);      // (49, 10) = 490 blocks
    fused_kernel<<<grid, TPB>>>(phi, POD, c, omega, z, zsin, zcos, ztanh,
                                sc, cc, tc, out_final, out_latent, out_z);
}

// round 15
// speedup vs baseline: 1.2499x; 1.2499x over previous
#include <cuda_runtime.h>

#define NN 100000
#define MM 1000
#define KA 11     // A rank terms (k=0 of original folded into B slot 0)
#define KB 12     // B floats per m: [0]=c0*z0 (acc init), [1..11] pair with A[0..10]
#define TPB 512
#define VN 4      // n per thread (float4 store)
#define MT 10     // m tiles
#define MC_MAX 100

typedef unsigned long long u64;

__device__ __forceinline__ u64 pack2(float lo, float hi) {
    u64 r; asm("mov.b64 %0, {%1,%2};" : "=l"(r) : "f"(lo), "f"(hi)); return r;
}
__device__ __forceinline__ u64 dup2(float v) {
    u64 r; asm("mov.b64 %0, {%1,%1};" : "=l"(r) : "f"(v)); return r;
}
__device__ __forceinline__ void unpack2(u64 v, float& lo, float& hi) {
    asm("mov.b64 {%0,%1}, %2;" : "=f"(lo), "=f"(hi) : "l"(v));
}
__device__ __forceinline__ u64 fma2(u64 a, u64 b, u64 c) {
    u64 d; asm("fma.rn.f32x2 %0, %1, %2, %3;" : "=l"(d) : "l"(a), "l"(b), "l"(c)); return d;
}
__device__ __forceinline__ float fast_sin(float x)  { float r; asm("sin.approx.f32 %0, %1;"  : "=f"(r) : "f"(x)); return r; }
__device__ __forceinline__ float fast_cos(float x)  { float r; asm("cos.approx.f32 %0, %1;"  : "=f"(r) : "f"(x)); return r; }
__device__ __forceinline__ float fast_tanh(float x) { float r; asm("tanh.approx.f32 %0, %1;" : "=f"(r) : "f"(x)); return r; }

// Fused rank-12 outer product. R10 engine (VN=4, 64 regs, 32 warps/SM, 3x
// LDS.128 + ALU dup per iteration) with TPB=512: half the CTA prologues /
// barriers for the same resident-warp geometry.
//   out[m*NN + n] = c0*z0[m] + sum_{k=0..10} A[n,k] * B[m,k+1]
__global__ void __launch_bounds__(TPB, 2)
fused_kernel(const float* __restrict__ phi, const float* __restrict__ POD,
             const float* __restrict__ c, const float* __restrict__ omega,
             const float* __restrict__ z, const float* __restrict__ zsin,
             const float* __restrict__ zcos, const float* __restrict__ ztanh,
             const float* __restrict__ sc, const float* __restrict__ cc,
             const float* __restrict__ tc,
             float* __restrict__ out_final, float* __restrict__ out_latent,
             float* __restrict__ out_z) {
    __shared__ __align__(16) float Bs[MC_MAX * KB];  // plain floats, 48B per m

    const int tid = threadIdx.x;
    const int mBase = blockIdx.y * MC_MAX;            // y in [0,10); MC*MT == MM

    // ---- B tile: threads 0..MC_MAX-1 compute one m row each ----
    if (tid < MC_MAX) {
        int m = mBase + tid;
        float* b = Bs + tid * KB;
        b[0] = c[0] * z[m];
#pragma unroll
        for (int t = 1; t < 6; t++) b[t] = z[t * MM + m];
        b[6]  = sc[0] * zsin[m];
        b[7]  = sc[1] * zsin[MM + m];
        b[8]  = cc[0] * zcos[m];
        b[9]  = cc[1] * zcos[MM + m];
        b[10] = tc[0] * ztanh[m];
        b[11] = tc[1] * ztanh[MM + m];
    }

    // ---- z_values copy (once, by block (0,0)) ----
    if (blockIdx.x == 0 && blockIdx.y == 0) {
        for (int i = tid; i < 6 * MM; i += TPB) out_z[i] = z[i];
    }
    __syncthreads();

    const int n0 = (blockIdx.x * TPB + tid) * VN;
    if (n0 >= NN) return;  // NN % 4 == 0; in-range threads write full float4

    // ---- A features inline for this thread's 4 n's ----
    float4 p0 = *(const float4*)(phi + n0);
    float4 p1 = *(const float4*)(phi + NN + n0);
    float4 qa = *(const float4*)(POD + 2 * n0);
    float4 qb = *(const float4*)(POD + 2 * n0 + 4);

    float y0[4], y1[4];
    y0[0] = p0.x * qa.x;  y1[0] = p1.x * qa.y;
    y0[1] = p0.y * qa.z;  y1[1] = p1.y * qa.w;
    y0[2] = p0.z * qb.x;  y1[2] = p1.z * qb.y;
    y0[3] = p0.w * qb.z;  y1[3] = p1.w * qb.w;

    if (blockIdx.y == 0) {  // latent_spatial (N,2): [y0, y1] interleaved
        *(float4*)(out_latent + 2 * n0)     = make_float4(y0[0], y1[0], y0[1], y1[1]);
        *(float4*)(out_latent + 2 * n0 + 4) = make_float4(y0[2], y1[2], y0[3], y1[3]);
    }

    float c1 = c[1], c2 = c[2], c3 = c[3], c4 = c[4], c5 = c[5];
    float w0 = omega[0], w1 = omega[1], w2 = omega[2];
    float w3 = omega[3], w4 = omega[4], w5 = omega[5];

    // Pack A features directly as f32x2 pairs (n0/n1 lane, n2/n3 lane).
    u64 pa01[KA], pa23[KA];
#define PACK_K(k, EXPR)                                                      \
    pa01[k] = pack2(EXPR(0), EXPR(1));                                       \
    pa23[k] = pack2(EXPR(2), EXPR(3));
#define F0(j)  (c1 * y0[j])
#define F1(j)  (c2 * y1[j])
#define F2(j)  (c3 * y0[j] * y0[j])
#define F3(j)  (c4 * y0[j] * y1[j])
#define F4(j)  (c5 * y1[j] * y1[j])
#define F5(j)  fast_sin(w0 * y0[j])
#define F6(j)  fast_sin(w3 * y1[j])
#define F7(j)  fast_cos(w1 * y0[j])
#define F8(j)  fast_cos(w4 * y1[j])
#define F9(j)  fast_tanh(w2 * y0[j])
#define F10(j) fast_tanh(w5 * y1[j])
    PACK_K(0, F0)  PACK_K(1, F1)  PACK_K(2, F2)  PACK_K(3, F3)
    PACK_K(4, F4)  PACK_K(5, F5)  PACK_K(6, F6)  PACK_K(7, F7)
    PACK_K(8, F8)  PACK_K(9, F9)  PACK_K(10, F10)

    // ---- main store stream ----
    float* outBase = out_final + (size_t)mBase * NN + n0;
#pragma unroll 4
    for (int mi = 0; mi < MC_MAX; ++mi) {
        const float4* bb = (const float4*)(Bs + mi * KB);  // 3x LDS.128 (broadcast)
        float4 q0 = bb[0];   // b0..b3
        float4 q1 = bb[1];   // b4..b7
        float4 q2 = bb[2];   // b8..b11

        u64 d0  = dup2(q0.x);                       // init = c0*z0[m]
        u64 d1  = dup2(q0.y);
        u64 acc01 = fma2(pa01[0], d1, d0);
        u64 acc23 = fma2(pa23[0], d1, d0);
        u64 d2  = dup2(q0.z);
        acc01 = fma2(pa01[1], d2, acc01);  acc23 = fma2(pa23[1], d2, acc23);
        u64 d3  = dup2(q0.w);
        acc01 = fma2(pa01[2], d3, acc01);  acc23 = fma2(pa23[2], d3, acc23);
        u64 d4  = dup2(q1.x);
        acc01 = fma2(pa01[3], d4, acc01);  acc23 = fma2(pa23[3], d4, acc23);
        u64 d5  = dup2(q1.y);
        acc01 = fma2(pa01[4], d5, acc01);  acc23 = fma2(pa23[4], d5, acc23);
        u64 d6  = dup2(q1.z);
        acc01 = fma2(pa01[5], d6, acc01);  acc23 = fma2(pa23[5], d6, acc23);
        u64 d7  = dup2(q1.w);
        acc01 = fma2(pa01[6], d7, acc01);  acc23 = fma2(pa23[6], d7, acc23);
        u64 d8  = dup2(q2.x);
        acc01 = fma2(pa01[7], d8, acc01);  acc23 = fma2(pa23[7], d8, acc23);
        u64 d9  = dup2(q2.y);
        acc01 = fma2(pa01[8], d9, acc01);  acc23 = fma2(pa23[8], d9, acc23);
        u64 d10 = dup2(q2.z);
        acc01 = fma2(pa01[9], d10, acc01); acc23 = fma2(pa23[9], d10, acc23);
        u64 d11 = dup2(q2.w);
        acc01 = fma2(pa01[10], d11, acc01); acc23 = fma2(pa23[10], d11, acc23);

        float4 o;
        unpack2(acc01, o.x, o.y);
        unpack2(acc23, o.z, o.w);
        __stcs((float4*)(outBase + (size_t)mi * NN), o);
    }
}

extern "C" void kernel_launch(void* const* d_in, const int* in_sizes, int n_in,
                              void* d_out, int out_size) {
    // Input order: X, phi, POD_modes, c_coef, z_values, zsin, zcos,
    //              ztanh, sin_coef, cos_coef, tanh_coef, omega
    const float* phi   = (const float*)d_in[1];
    const float* POD   = (const float*)d_in[2];
    const float* c     = (const float*)d_in[3];
    const float* z     = (const float*)d_in[4];
    const float* zsin  = (const float*)d_in[5];
    const float* zcos  = (const float*)d_in[6];
    const float* ztanh = (const float*)d_in[7];
    const float* sc    = (const float*)d_in[8];
    const float* cc    = (const float*)d_in[9];
    const float* tc    = (const float*)d_in[10];
    const float* omega = (const float*)d_in[11];

    float* out        = (float*)d_out;
    float* out_final  = out;                              // (M, N)
    float* out_latent = out + (size_t)MM * NN;            // (N, 2)
    float* out_z      = out_latent + (size_t)NN * 2;      // (6, M)

    dim3 grid((NN + TPB * VN - 1) / (TPB * VN), MT);      // (49, 10) = 490 blocks
    fused_kernel<<<grid, TPB>>>(phi, POD, c, omega, z, zsin, zcos, ztanh,
                                sc, cc, tc, out_final, out_latent, out_z);
}